// round 14
// baseline (speedup 1.0000x reference)
#include <cuda_runtime.h>
#include <cuda_fp16.h>
#include <stdint.h>

#define MAXN    1048576        // >= 1,000,000 rows
#define KTAPS   27
#define CIN     32
#define COUT    32
#define MBLOCK  256            // rows per tile (4 warps x 64 rows)
#define NTHREADS 128

// Scratch (allocation-free): fp16 copy of X with permuted channel pairs, fp16 W.
__device__ __align__(128) __half g_x16[(size_t)MAXN * CIN];           // 64 MiB
__device__ __align__(16) __half g_w16[KTAPS * COUT * CIN];            // [tap][n][k'] 54 KiB
__device__ int g_nbr_is64;                                            // neighbor dtype flag

// Involution on channel-pair index (s in 0..15): sigma(sigma(s)) == s
__device__ __forceinline__ int sigma(int s) { return ((s & 3) << 2) | (s >> 2); }

// ---------------- Fused prep: X convert + W convert + nbr dtype detect ----------------
__global__ void prep_kernel(const float* __restrict__ x,
                            const float* __restrict__ w,
                            const int*   __restrict__ nbr_words, int n) {
    // X conversion: fp32 [N,32] -> fp16 permuted [N,32]
    long long tid = (long long)blockIdx.x * blockDim.x + threadIdx.x;
    long long total = (long long)n * 16;
    if (tid < total) {
        int i = (int)(tid >> 4);
        int s = (int)(tid & 15);
        int p = sigma(s);                      // memory slot s holds original pair sigma(s)
        float2 v = __ldcs((const float2*)(x + (size_t)i * CIN + 2 * p));
        ((__half2*)g_x16)[(size_t)i * 16 + s] = __floats2half2_rn(v.x, v.y);
    }
    // W conversion (first 108 blocks)
    if (blockIdx.x < (KTAPS * COUT * CIN + 255) / 256) {
        int e = blockIdx.x * 256 + threadIdx.x;
        if (e < KTAPS * COUT * CIN) {
            int tap = e / (COUT * CIN);
            int rem = e % (COUT * CIN);
            int nn  = rem / CIN;
            int kp  = rem % CIN;               // permuted k position
            int s   = kp >> 1, bit = kp & 1;
            int c   = 2 * sigma(s) + bit;      // original input channel
            g_w16[e] = __float2half_rn(w[(size_t)tap * CIN * COUT + (size_t)c * COUT + nn]);
        }
    }
    // nbr dtype detect (block 0): int64 LE nonneg -> odd int32 words all zero
    if (blockIdx.x == 0) {
        int nz = 0;
        #pragma unroll
        for (int j = 0; j < 8; j++)
            nz |= nbr_words[2 * (threadIdx.x * 8 + j) + 1];
        int any = __syncthreads_or(nz != 0);
        if (threadIdx.x == 0) g_nbr_is64 = any ? 0 : 1;
    }
}

// ---------------- fp16 MMA m16n8k16, fp32 accumulate ----------------
__device__ __forceinline__ void mma16816(float c[4],
                                         uint32_t a0, uint32_t a1, uint32_t a2, uint32_t a3,
                                         uint32_t b0, uint32_t b1) {
    asm("mma.sync.aligned.m16n8k16.row.col.f32.f16.f16.f32 "
        "{%0,%1,%2,%3}, {%4,%5,%6,%7}, {%8,%9}, {%0,%1,%2,%3};\n"
        : "+f"(c[0]), "+f"(c[1]), "+f"(c[2]), "+f"(c[3])
        : "r"(a0), "r"(a1), "r"(a2), "r"(a3), "r"(b0), "r"(b1));
}

// ---------------- Main: 4 warps x 64 rows, B-LDS amortized 2x, depth-2 pipeline ----
// smem: [0, 55296)          fp16 W (uint4 view, [tap][n-tile-row][16B])
//       [55296, 82944)      int32 neighbor BYTE OFFSETS (idx*64) [256 rows][27 taps]
#define W_SMEM     55296
#define SMEM_BYTES (W_SMEM + MBLOCK * KTAPS * 4)

__global__ __launch_bounds__(NTHREADS, 2)
void conv_main_kernel(const void* __restrict__ nbr_raw,
                      const float* __restrict__ bias,
                      float* __restrict__ out, int n, int ntiles) {
    extern __shared__ uint8_t smem[];
    uint4* w_s4  = (uint4*)smem;
    int*   nbr_s = (int*)(smem + W_SMEM);

    const int tid  = threadIdx.x;
    const int is64 = g_nbr_is64;

    // Stage W once per persistent block (3456 uint4, coalesced, 27/thread)
    const uint4* wg4 = (const uint4*)g_w16;
    #pragma unroll 4
    for (int t = tid; t < 3456; t += NTHREADS) w_s4[t] = wg4[t];

    const int lane = tid & 31;
    const int warp = tid >> 5;
    const int q    = lane & 3;     // quad column (16B chunk within row)
    const int nrow = lane >> 2;    // 0..7
    const int mb   = warp * 64;    // warp's 64 rows within tile

    // Bias fragment (kept in regs across tiles)
    float2 bz[4];
    #pragma unroll
    for (int t = 0; t < 4; t++)
        bz[t] = *(const float2*)(bias + t * 8 + 2 * q);

    const char* xb = (const char*)g_x16 + q * 16;   // this thread's chunk base

    // One tap's A gather: 4 m-tiles (64 rows) -> 8 LDG.128 per lane
    #define LOAD_TAP(buf, k) do {                                           \
        _Pragma("unroll")                                                   \
        for (int mt = 0; mt < 4; mt++) {                                    \
            int rlo = mb + mt * 16 + nrow;                                  \
            int olo = nbr_s[rlo * KTAPS + (k)];                             \
            int ohi = nbr_s[(rlo + 8) * KTAPS + (k)];                       \
            (buf)[mt * 2 + 0] = *(const uint4*)(xb + olo);                  \
            (buf)[mt * 2 + 1] = *(const uint4*)(xb + ohi);                  \
        }                                                                   \
    } while (0)

    // One tap's MMAs: 4 n-tiles x 4 m-tiles x 2 k-chunks; one B LDS.128 per n-tile
    #define MMA_TAP(buf, k) do {                                            \
        _Pragma("unroll")                                                   \
        for (int t = 0; t < 4; t++) {                                       \
            uint4 bw = w_s4[(k) * 128 + (t * 8 + nrow) * 4 + q];            \
            _Pragma("unroll")                                               \
            for (int mt = 0; mt < 4; mt++) {                                \
                const uint4& lo = (buf)[mt * 2 + 0];                        \
                const uint4& hi = (buf)[mt * 2 + 1];                        \
                mma16816(acc[mt][t], lo.x, hi.x, lo.y, hi.y, bw.x, bw.y);   \
                mma16816(acc[mt][t], lo.z, hi.z, lo.w, hi.w, bw.z, bw.w);   \
            }                                                               \
        }                                                                   \
    } while (0)

    for (int tile = blockIdx.x; tile < ntiles; tile += gridDim.x) {
        const int i0 = tile * MBLOCK;

        __syncthreads();   // previous tile's readers done before nbr_s overwrite
        // Stage neighbor byte-offsets (idx*64), coalesced, tail-guarded (54/thread).
        if (is64) {
            const long long* nbr = (const long long*)nbr_raw;
            for (int t = tid; t < MBLOCK * KTAPS; t += NTHREADS) {
                int r = t / KTAPS;
                long long v = (i0 + r < n) ? __ldcs(nbr + (size_t)i0 * KTAPS + t) : 0;
                nbr_s[t] = ((int)v) << 6;
            }
        } else {
            const int* nbr = (const int*)nbr_raw;
            for (int t = tid; t < MBLOCK * KTAPS; t += NTHREADS) {
                int r = t / KTAPS;
                int v = (i0 + r < n) ? __ldcs(nbr + (size_t)i0 * KTAPS + t) : 0;
                nbr_s[t] = v << 6;
            }
        }
        __syncthreads();

        // Acc init = bias (64 floats)
        float acc[4][4][4];
        #pragma unroll
        for (int t = 0; t < 4; t++) {
            #pragma unroll
            for (int mt = 0; mt < 4; mt++) {
                acc[mt][t][0] = bz[t].x; acc[mt][t][1] = bz[t].y;
                acc[mt][t][2] = bz[t].x; acc[mt][t][3] = bz[t].y;
            }
        }

        // Depth-2 software pipeline, 3 rotating register buffers (8 uint4 each),
        // KTAPS = 9*3 so buffer indices are compile-time.
        uint4 A0[8], A1[8], A2[8];
        LOAD_TAP(A0, 0);
        LOAD_TAP(A1, 1);

        #pragma unroll 1
        for (int kk = 0; kk < KTAPS / 3; kk++) {
            int k = kk * 3;
            if (k + 2 < KTAPS) LOAD_TAP(A2, k + 2);
            MMA_TAP(A0, k);
            if (k + 3 < KTAPS) LOAD_TAP(A0, k + 3);
            MMA_TAP(A1, k + 1);
            if (k + 4 < KTAPS) LOAD_TAP(A1, k + 4);
            MMA_TAP(A2, k + 2);
        }

        // Epilogue: streaming stores (bias already in acc)
        #pragma unroll
        for (int mt = 0; mt < 4; mt++) {
            #pragma unroll
            for (int half = 0; half < 2; half++) {
                int r = i0 + mb + mt * 16 + nrow + half * 8;
                if (r < n) {
                    float* po = out + (size_t)r * COUT + 2 * q;
                    #pragma unroll
                    for (int t = 0; t < 4; t++) {
                        float2 v;
                        v.x = acc[mt][t][half * 2 + 0];
                        v.y = acc[mt][t][half * 2 + 1];
                        __stcs((float2*)(po + t * 8), v);
                    }
                }
            }
        }
    }
}

// ---------------- Launch ----------------
extern "C" void kernel_launch(void* const* d_in, const int* in_sizes, int n_in,
                              void* d_out, int out_size) {
    const float* x    = (const float*)d_in[0];       // [N, 32] f32
    const float* w    = (const float*)d_in[1];       // [27, 32, 32] f32
    const float* bias = (const float*)d_in[2];       // [32] f32
    const void*  nbr  = d_in[3];                     // [N, 27] int32 OR int64 (detected)
    float*       out  = (float*)d_out;               // [N, 32] f32

    const int n = in_sizes[0] / CIN;
    const int ntiles = (n + MBLOCK - 1) / MBLOCK;

    int nsm = 148;
    cudaDeviceGetAttribute(&nsm, cudaDevAttrMultiProcessorCount, 0);
    int grid = 2 * nsm;
    if (grid > ntiles) grid = ntiles;

    cudaFuncSetAttribute(conv_main_kernel,
                         cudaFuncAttributeMaxDynamicSharedMemorySize, SMEM_BYTES);

    {
        long long total = (long long)n * 16;
        int blocks = (int)((total + 255) / 256);
        prep_kernel<<<blocks, 256>>>(x, w, (const int*)nbr, n);
    }
    conv_main_kernel<<<grid, NTHREADS, SMEM_BYTES>>>(nbr, bias, out, n, ntiles);
}

// round 15
// speedup vs baseline: 1.3481x; 1.3481x over previous
#include <cuda_runtime.h>
#include <cuda_fp16.h>
#include <stdint.h>

#define MAXN    1048576        // >= 1,000,000 rows
#define KTAPS   27
#define CIN     32
#define COUT    32
#define MBLOCK  256            // rows per tile (2 m16-tiles x 16 rows per warp)
#define NTHREADS 256

// Scratch (allocation-free): fp16 copy of X with permuted channel pairs, fp16 W.
__device__ __align__(128) __half g_x16[(size_t)MAXN * CIN];           // 64 MiB
__device__ __align__(16) __half g_w16[KTAPS * COUT * CIN];            // [tap][n][k'] 54 KiB
__device__ int g_nbr_is64;                                            // neighbor dtype flag

// Involution on channel-pair index (s in 0..15): sigma(sigma(s)) == s
__device__ __forceinline__ int sigma(int s) { return ((s & 3) << 2) | (s >> 2); }

// ---------------- Fused prep: X convert + W convert + nbr dtype detect ----------------
// 8 threads per row; each thread: one float4 (16B) __ldcs load + one 8B store.
// Thread u (0..7) covers fp32 channel pair indices (2u, 2u+1) = pairs p0=2u? No:
// float4 at x[row*32 + u*4] covers channels 4u..4u+3 = pairs (2u, 2u+1).
// Destination slots: s with sigma(s)=2u and sigma(s')=2u+1.
__global__ void prep_kernel(const float4* __restrict__ x4,
                            const float* __restrict__ w,
                            const int*   __restrict__ nbr_words, int n) {
    long long tid = (long long)blockIdx.x * blockDim.x + threadIdx.x;
    long long total = (long long)n * 8;
    if (tid < total) {
        int i = (int)(tid >> 3);
        int u = (int)(tid & 7);
        float4 v = __ldcs(x4 + (size_t)i * 8 + u);
        // pairs 2u and 2u+1 -> slots sigma(2u), sigma(2u+1) (sigma is involution)
        int s0 = sigma(2 * u);
        int s1 = sigma(2 * u + 1);
        __half2* dst = (__half2*)g_x16 + (size_t)i * 16;
        dst[s0] = __floats2half2_rn(v.x, v.y);
        dst[s1] = __floats2half2_rn(v.z, v.w);
    }
    // W conversion (first 54 blocks of 512 threads)
    if (blockIdx.x < (KTAPS * COUT * CIN + 511) / 512) {
        int e = blockIdx.x * 512 + threadIdx.x;
        if (e < KTAPS * COUT * CIN) {
            int tap = e / (COUT * CIN);
            int rem = e % (COUT * CIN);
            int nn  = rem / CIN;
            int kp  = rem % CIN;               // permuted k position
            int s   = kp >> 1, bit = kp & 1;
            int c   = 2 * sigma(s) + bit;      // original input channel
            g_w16[e] = __float2half_rn(w[(size_t)tap * CIN * COUT + (size_t)c * COUT + nn]);
        }
    }
    // nbr dtype detect (block 0, first 256 threads):
    // int64 LE nonneg -> odd int32 words all zero; int32 -> random nonzero.
    if (blockIdx.x == 0 && threadIdx.x < 256) {
        int nz = 0;
        #pragma unroll
        for (int j = 0; j < 8; j++)
            nz |= nbr_words[2 * (threadIdx.x * 8 + j) + 1];
        unsigned any = __ballot_sync(0xFFFFFFFFu, nz != 0);
        // combine across the 8 participating warps via shared flag
        __shared__ int s_any;
        if (threadIdx.x == 0) s_any = 0;
        __syncthreads();
        if (any && (threadIdx.x & 31) == 0) atomicOr(&s_any, 1);
        __syncthreads();
        if (threadIdx.x == 0) g_nbr_is64 = s_any ? 0 : 1;
    }
}

// ---------------- fp16 MMA m16n8k16, fp32 accumulate ----------------
__device__ __forceinline__ void mma16816(float c[4],
                                         uint32_t a0, uint32_t a1, uint32_t a2, uint32_t a3,
                                         uint32_t b0, uint32_t b1) {
    asm("mma.sync.aligned.m16n8k16.row.col.f32.f16.f16.f32 "
        "{%0,%1,%2,%3}, {%4,%5,%6,%7}, {%8,%9}, {%0,%1,%2,%3};\n"
        : "+f"(c[0]), "+f"(c[1]), "+f"(c[2]), "+f"(c[3])
        : "r"(a0), "r"(a1), "r"(a2), "r"(a3), "r"(b0), "r"(b1));
}

// ---------------- Main: FROZEN at the R11 configuration (measured 244 us) ----------
// smem: [0, 55296)          fp16 W (uint4 view, [tap][n-tile-row][16B])
//       [55296, 82944)      int32 neighbor BYTE OFFSETS (idx*64) [256 rows][27 taps]
#define W_SMEM     55296
#define SMEM_BYTES (W_SMEM + MBLOCK * KTAPS * 4)

__global__ __launch_bounds__(NTHREADS, 2)
void conv_main_kernel(const void* __restrict__ nbr_raw,
                      const float* __restrict__ bias,
                      float* __restrict__ out, int n, int ntiles) {
    extern __shared__ uint8_t smem[];
    uint4* w_s4  = (uint4*)smem;
    int*   nbr_s = (int*)(smem + W_SMEM);

    const int tid  = threadIdx.x;
    const int is64 = g_nbr_is64;

    // Stage W once per persistent block (3456 uint4, coalesced)
    const uint4* wg4 = (const uint4*)g_w16;
    #pragma unroll 4
    for (int t = tid; t < 3456; t += NTHREADS) w_s4[t] = wg4[t];

    const int lane = tid & 31;
    const int warp = tid >> 5;
    const int q    = lane & 3;     // quad column (16B chunk within row)
    const int nrow = lane >> 2;    // 0..7
    const int mb   = warp * 32;    // warp's 32 rows within tile

    // Bias fragment (kept in regs across tiles)
    float2 bz[4];
    #pragma unroll
    for (int t = 0; t < 4; t++)
        bz[t] = *(const float2*)(bias + t * 8 + 2 * q);

    const char* xb = (const char*)g_x16 + q * 16;   // this thread's chunk base

    #define LOAD_TAP(buf, k) do {                                           \
        _Pragma("unroll")                                                   \
        for (int mt = 0; mt < 2; mt++) {                                    \
            int rlo = mb + mt * 16 + nrow;                                  \
            int olo = nbr_s[rlo * KTAPS + (k)];                             \
            int ohi = nbr_s[(rlo + 8) * KTAPS + (k)];                       \
            (buf)[mt * 2 + 0] = *(const uint4*)(xb + olo);                  \
            (buf)[mt * 2 + 1] = *(const uint4*)(xb + ohi);                  \
        }                                                                   \
    } while (0)

    #define MMA_TAP(buf, k) do {                                            \
        _Pragma("unroll")                                                   \
        for (int t = 0; t < 4; t++) {                                       \
            uint4 bw = w_s4[(k) * 128 + (t * 8 + nrow) * 4 + q];            \
            _Pragma("unroll")                                               \
            for (int mt = 0; mt < 2; mt++) {                                \
                const uint4& lo = (buf)[mt * 2 + 0];                        \
                const uint4& hi = (buf)[mt * 2 + 1];                        \
                mma16816(acc[mt][t], lo.x, hi.x, lo.y, hi.y, bw.x, bw.y);   \
                mma16816(acc[mt][t], lo.z, hi.z, lo.w, hi.w, bw.z, bw.w);   \
            }                                                               \
        }                                                                   \
    } while (0)

    for (int tile = blockIdx.x; tile < ntiles; tile += gridDim.x) {
        const int i0 = tile * MBLOCK;

        __syncthreads();   // previous tile's readers done before nbr_s overwrite
        // Stage neighbor byte-offsets (idx*64), coalesced, tail-guarded.
        if (is64) {
            const long long* nbr = (const long long*)nbr_raw;
            for (int t = tid; t < MBLOCK * KTAPS; t += NTHREADS) {
                int r = t / KTAPS;
                long long v = (i0 + r < n) ? __ldcs(nbr + (size_t)i0 * KTAPS + t) : 0;
                nbr_s[t] = ((int)v) << 6;
            }
        } else {
            const int* nbr = (const int*)nbr_raw;
            for (int t = tid; t < MBLOCK * KTAPS; t += NTHREADS) {
                int r = t / KTAPS;
                int v = (i0 + r < n) ? __ldcs(nbr + (size_t)i0 * KTAPS + t) : 0;
                nbr_s[t] = v << 6;
            }
        }
        __syncthreads();

        // Acc init = bias
        float acc[2][4][4];
        #pragma unroll
        for (int t = 0; t < 4; t++) {
            #pragma unroll
            for (int mt = 0; mt < 2; mt++) {
                acc[mt][t][0] = bz[t].x; acc[mt][t][1] = bz[t].y;
                acc[mt][t][2] = bz[t].x; acc[mt][t][3] = bz[t].y;
            }
        }

        // Depth-2 software pipeline, 3 rotating register buffers, KTAPS = 9*3.
        uint4 A0[4], A1[4], A2[4];
        LOAD_TAP(A0, 0);
        LOAD_TAP(A1, 1);

        #pragma unroll 1
        for (int kk = 0; kk < KTAPS / 3; kk++) {
            int k = kk * 3;
            if (k + 2 < KTAPS) LOAD_TAP(A2, k + 2);
            MMA_TAP(A0, k);
            if (k + 3 < KTAPS) LOAD_TAP(A0, k + 3);
            MMA_TAP(A1, k + 1);
            if (k + 4 < KTAPS) LOAD_TAP(A1, k + 4);
            MMA_TAP(A2, k + 2);
        }

        // Epilogue: streaming stores (bias already in acc)
        #pragma unroll
        for (int mt = 0; mt < 2; mt++) {
            #pragma unroll
            for (int half = 0; half < 2; half++) {
                int r = i0 + mb + mt * 16 + nrow + half * 8;
                if (r < n) {
                    float* po = out + (size_t)r * COUT + 2 * q;
                    #pragma unroll
                    for (int t = 0; t < 4; t++) {
                        float2 v;
                        v.x = acc[mt][t][half * 2 + 0];
                        v.y = acc[mt][t][half * 2 + 1];
                        __stcs((float2*)(po + t * 8), v);
                    }
                }
            }
        }
    }
}

// ---------------- Launch ----------------
extern "C" void kernel_launch(void* const* d_in, const int* in_sizes, int n_in,
                              void* d_out, int out_size) {
    const float* x    = (const float*)d_in[0];       // [N, 32] f32
    const float* w    = (const float*)d_in[1];       // [27, 32, 32] f32
    const float* bias = (const float*)d_in[2];       // [32] f32
    const void*  nbr  = d_in[3];                     // [N, 27] int32 OR int64 (detected)
    float*       out  = (float*)d_out;               // [N, 32] f32

    const int n = in_sizes[0] / CIN;
    const int ntiles = (n + MBLOCK - 1) / MBLOCK;

    int nsm = 148;
    cudaDeviceGetAttribute(&nsm, cudaDevAttrMultiProcessorCount, 0);
    int grid = 2 * nsm;
    if (grid > ntiles) grid = ntiles;

    cudaFuncSetAttribute(conv_main_kernel,
                         cudaFuncAttributeMaxDynamicSharedMemorySize, SMEM_BYTES);

    {
        long long total = (long long)n * 8;          // 8 threads per row
        int blocks = (int)((total + 511) / 512);
        prep_kernel<<<blocks, 512>>>((const float4*)x, w, (const int*)nbr, n);
    }
    conv_main_kernel<<<grid, NTHREADS, SMEM_BYTES>>>(nbr, bias, out, n, ntiles);
}

// round 16
// speedup vs baseline: 1.4928x; 1.1073x over previous
#include <cuda_runtime.h>
#include <cuda_fp16.h>
#include <stdint.h>

#define MAXN    1048576        // >= 1,000,000 rows
#define KTAPS   27
#define CIN     32
#define COUT    32
#define MBLOCK  256            // rows per tile (2 m16-tiles x 16 rows per warp)
#define NTHREADS 256

// Scratch (allocation-free): fp16 copy of X with permuted channel pairs, fp16 W.
__device__ __align__(128) __half g_x16[(size_t)MAXN * CIN];           // 64 MiB
__device__ __align__(16) __half g_w16[KTAPS * COUT * CIN];            // [tap][n][k'] 54 KiB

// Involution on channel-pair index (s in 0..15): sigma(sigma(s)) == s
__device__ __forceinline__ int sigma(int s) { return ((s & 3) << 2) | (s >> 2); }

// ---------------- Fused prep: X convert + W convert ----------------
// 8 threads per row; each thread: one float4 (16B) __ldcs load + two 8B stores.
__global__ void prep_kernel(const float4* __restrict__ x4,
                            const float* __restrict__ w, int n) {
    long long tid = (long long)blockIdx.x * blockDim.x + threadIdx.x;
    long long total = (long long)n * 8;
    if (tid < total) {
        int i = (int)(tid >> 3);
        int u = (int)(tid & 7);
        float4 v = __ldcs(x4 + (size_t)i * 8 + u);
        int s0 = sigma(2 * u);
        int s1 = sigma(2 * u + 1);
        __half2* dst = (__half2*)g_x16 + (size_t)i * 16;
        dst[s0] = __floats2half2_rn(v.x, v.y);
        dst[s1] = __floats2half2_rn(v.z, v.w);
    }
    // W conversion (first 54 blocks of 512 threads)
    if (blockIdx.x < (KTAPS * COUT * CIN + 511) / 512) {
        int e = blockIdx.x * 512 + threadIdx.x;
        if (e < KTAPS * COUT * CIN) {
            int tap = e / (COUT * CIN);
            int rem = e % (COUT * CIN);
            int nn  = rem / CIN;
            int kp  = rem % CIN;               // permuted k position
            int s   = kp >> 1, bit = kp & 1;
            int c   = 2 * sigma(s) + bit;      // original input channel
            g_w16[e] = __float2half_rn(w[(size_t)tap * CIN * COUT + (size_t)c * COUT + nn]);
        }
    }
}

// ---------------- fp16 MMA m16n8k16, fp32 accumulate ----------------
__device__ __forceinline__ void mma16816(float c[4],
                                         uint32_t a0, uint32_t a1, uint32_t a2, uint32_t a3,
                                         uint32_t b0, uint32_t b1) {
    asm("mma.sync.aligned.m16n8k16.row.col.f32.f16.f16.f32 "
        "{%0,%1,%2,%3}, {%4,%5,%6,%7}, {%8,%9}, {%0,%1,%2,%3};\n"
        : "+f"(c[0]), "+f"(c[1]), "+f"(c[2]), "+f"(c[3])
        : "r"(a0), "r"(a1), "r"(a2), "r"(a3), "r"(b0), "r"(b1));
}

// ---------------- Main: frozen R11 loop; PDL prologue; div-free staging ----------
// smem: [0, 55296)          fp16 W (uint4 view, [tap][n-tile-row][16B])
//       [55296, 82944)      int32 neighbor BYTE OFFSETS (idx*64) [256 rows][27 taps]
#define W_SMEM     55296
#define SMEM_BYTES (W_SMEM + MBLOCK * KTAPS * 4)

__global__ __launch_bounds__(NTHREADS, 2)
void conv_main_kernel(const void* __restrict__ nbr_raw,
                      const float* __restrict__ bias,
                      float* __restrict__ out, int n, int ntiles) {
    extern __shared__ uint8_t smem[];
    uint4* w_s4  = (uint4*)smem;
    int*   nbr_s = (int*)(smem + W_SMEM);

    const int tid = threadIdx.x;

    // --- block-local nbr dtype detect (reads harness input only, pre-PDL-wait) ---
    // int64 LE nonneg -> all odd int32 words zero; int32 -> random nonzero.
    int nz = 0;
    {
        const int* words = (const int*)nbr_raw;
        nz |= words[2 * (tid * 2 + 0) + 1];
        nz |= words[2 * (tid * 2 + 1) + 1];
    }
    const int is64 = __syncthreads_or(nz != 0) ? 0 : 1;

    // Staging: full tiles are layout-identical to source -> division-free.
    #define STAGE_NBR(i0_) do {                                                    \
        if ((i0_) + MBLOCK <= n) {                                                 \
            if (is64) {                                                            \
                const long long* g_ = (const long long*)nbr_raw + (size_t)(i0_) * KTAPS; \
                for (int t_ = tid; t_ < MBLOCK * KTAPS; t_ += NTHREADS)            \
                    nbr_s[t_] = ((int)__ldcs(g_ + t_)) << 6;                       \
            } else {                                                               \
                const int* g_ = (const int*)nbr_raw + (size_t)(i0_) * KTAPS;       \
                for (int t_ = tid; t_ < MBLOCK * KTAPS; t_ += NTHREADS)            \
                    nbr_s[t_] = __ldcs(g_ + t_) << 6;                              \
            }                                                                      \
        } else {                                                                   \
            if (is64) {                                                            \
                const long long* g_ = (const long long*)nbr_raw + (size_t)(i0_) * KTAPS; \
                for (int t_ = tid; t_ < MBLOCK * KTAPS; t_ += NTHREADS) {          \
                    int r_ = t_ / KTAPS;                                           \
                    long long v_ = ((i0_) + r_ < n) ? __ldcs(g_ + t_) : 0;         \
                    nbr_s[t_] = ((int)v_) << 6;                                    \
                }                                                                  \
            } else {                                                               \
                const int* g_ = (const int*)nbr_raw + (size_t)(i0_) * KTAPS;       \
                for (int t_ = tid; t_ < MBLOCK * KTAPS; t_ += NTHREADS) {          \
                    int r_ = t_ / KTAPS;                                           \
                    int v_ = ((i0_) + r_ < n) ? __ldcs(g_ + t_) : 0;               \
                    nbr_s[t_] = v_ << 6;                                           \
                }                                                                  \
            }                                                                      \
        }                                                                          \
    } while (0)

    // Pre-stage tile 0's neighbors (input-only) while prep may still be running.
    STAGE_NBR(blockIdx.x * MBLOCK);

    // Wait for prep grid (g_x16, g_w16) before touching its outputs.
    asm volatile("griddepcontrol.wait;" ::: "memory");

    // Stage W once per persistent block (3456 uint4, coalesced)
    const uint4* wg4 = (const uint4*)g_w16;
    #pragma unroll 4
    for (int t = tid; t < 3456; t += NTHREADS) w_s4[t] = wg4[t];

    const int lane = tid & 31;
    const int warp = tid >> 5;
    const int q    = lane & 3;     // quad column (16B chunk within row)
    const int nrow = lane >> 2;    // 0..7
    const int mb   = warp * 32;    // warp's 32 rows within tile

    // Bias fragment (kept in regs across tiles)
    float2 bz[4];
    #pragma unroll
    for (int t = 0; t < 4; t++)
        bz[t] = *(const float2*)(bias + t * 8 + 2 * q);

    const char* xb = (const char*)g_x16 + q * 16;   // this thread's chunk base

    #define LOAD_TAP(buf, k) do {                                           \
        _Pragma("unroll")                                                   \
        for (int mt = 0; mt < 2; mt++) {                                    \
            int rlo = mb + mt * 16 + nrow;                                  \
            int olo = nbr_s[rlo * KTAPS + (k)];                             \
            int ohi = nbr_s[(rlo + 8) * KTAPS + (k)];                       \
            (buf)[mt * 2 + 0] = *(const uint4*)(xb + olo);                  \
            (buf)[mt * 2 + 1] = *(const uint4*)(xb + ohi);                  \
        }                                                                   \
    } while (0)

    #define MMA_TAP(buf, k) do {                                            \
        _Pragma("unroll")                                                   \
        for (int t = 0; t < 4; t++) {                                       \
            uint4 bw = w_s4[(k) * 128 + (t * 8 + nrow) * 4 + q];            \
            _Pragma("unroll")                                               \
            for (int mt = 0; mt < 2; mt++) {                                \
                const uint4& lo = (buf)[mt * 2 + 0];                        \
                const uint4& hi = (buf)[mt * 2 + 1];                        \
                mma16816(acc[mt][t], lo.x, hi.x, lo.y, hi.y, bw.x, bw.y);   \
                mma16816(acc[mt][t], lo.z, hi.z, lo.w, hi.w, bw.z, bw.w);   \
            }                                                               \
        }                                                                   \
    } while (0)

    __syncthreads();   // W + tile-0 nbr visible to all warps

    for (int tile = blockIdx.x; tile < ntiles; tile += gridDim.x) {
        const int i0 = tile * MBLOCK;

        // Acc init = bias
        float acc[2][4][4];
        #pragma unroll
        for (int t = 0; t < 4; t++) {
            #pragma unroll
            for (int mt = 0; mt < 2; mt++) {
                acc[mt][t][0] = bz[t].x; acc[mt][t][1] = bz[t].y;
                acc[mt][t][2] = bz[t].x; acc[mt][t][3] = bz[t].y;
            }
        }

        // Depth-2 software pipeline, 3 rotating register buffers, KTAPS = 9*3.
        uint4 A0[4], A1[4], A2[4];
        LOAD_TAP(A0, 0);
        LOAD_TAP(A1, 1);

        #pragma unroll 1
        for (int kk = 0; kk < KTAPS / 3; kk++) {
            int k = kk * 3;
            if (k + 2 < KTAPS) LOAD_TAP(A2, k + 2);
            MMA_TAP(A0, k);
            if (k + 3 < KTAPS) LOAD_TAP(A0, k + 3);
            MMA_TAP(A1, k + 1);
            if (k + 4 < KTAPS) LOAD_TAP(A1, k + 4);
            MMA_TAP(A2, k + 2);
        }

        // Epilogue: streaming stores (bias already in acc)
        #pragma unroll
        for (int mt = 0; mt < 2; mt++) {
            #pragma unroll
            for (int half = 0; half < 2; half++) {
                int r = i0 + mb + mt * 16 + nrow + half * 8;
                if (r < n) {
                    float* po = out + (size_t)r * COUT + 2 * q;
                    #pragma unroll
                    for (int t = 0; t < 4; t++) {
                        float2 v;
                        v.x = acc[mt][t][half * 2 + 0];
                        v.y = acc[mt][t][half * 2 + 1];
                        __stcs((float2*)(po + t * 8), v);
                    }
                }
            }
        }

        // Stage next tile's neighbors (loop-bottom, barrier-bracketed)
        const int nxt = tile + gridDim.x;
        if (nxt < ntiles) {
            __syncthreads();                 // all warps done reading nbr_s
            STAGE_NBR(nxt * MBLOCK);
            __syncthreads();                 // staged data visible
        }
    }
}

// ---------------- Launch ----------------
extern "C" void kernel_launch(void* const* d_in, const int* in_sizes, int n_in,
                              void* d_out, int out_size) {
    const float* x    = (const float*)d_in[0];       // [N, 32] f32
    const float* w    = (const float*)d_in[1];       // [27, 32, 32] f32
    const float* bias = (const float*)d_in[2];       // [32] f32
    const void*  nbr  = d_in[3];                     // [N, 27] int32 OR int64 (detected)
    float*       out  = (float*)d_out;               // [N, 32] f32

    const int n = in_sizes[0] / CIN;
    const int ntiles = (n + MBLOCK - 1) / MBLOCK;

    int nsm = 148;
    cudaDeviceGetAttribute(&nsm, cudaDevAttrMultiProcessorCount, 0);
    int grid = 2 * nsm;
    if (grid > ntiles) grid = ntiles;

    cudaFuncSetAttribute(conv_main_kernel,
                         cudaFuncAttributeMaxDynamicSharedMemorySize, SMEM_BYTES);

    {
        long long total = (long long)n * 8;          // 8 threads per row
        int blocks = (int)((total + 511) / 512);
        prep_kernel<<<blocks, 512>>>((const float4*)x, w, n);
    }

    // Main kernel with programmatic dependent launch: prologue (dtype detect +
    // tile-0 nbr staging) overlaps prep's tail; griddepcontrol.wait gates g_x16/g_w16.
    {
        cudaLaunchConfig_t cfg = {};
        cfg.gridDim  = dim3(grid, 1, 1);
        cfg.blockDim = dim3(NTHREADS, 1, 1);
        cfg.dynamicSmemBytes = SMEM_BYTES;
        cfg.stream = 0;
        cudaLaunchAttribute attr[1];
        attr[0].id = cudaLaunchAttributeProgrammaticStreamSerialization;
        attr[0].val.programmaticStreamSerializationAllowed = 1;
        cfg.attrs = attr;
        cfg.numAttrs = 1;
        cudaError_t err = cudaLaunchKernelEx(&cfg, conv_main_kernel,
                                             nbr, bias, out, n, ntiles);
        if (err != cudaSuccess) {
            // Fallback: plain launch (griddepcontrol.wait is a no-op without PDL)
            conv_main_kernel<<<grid, NTHREADS, SMEM_BYTES>>>(nbr, bias, out, n, ntiles);
        }
    }
}

// round 17
// speedup vs baseline: 1.5101x; 1.0116x over previous
#include <cuda_runtime.h>
#include <cuda_fp16.h>
#include <stdint.h>

#define MAXN    1048576        // >= 1,000,000 rows
#define KTAPS   27
#define CIN     32
#define COUT    32
#define MBLOCK  256            // rows per tile (2 m16-tiles x 16 rows per warp)
#define NTHREADS 256

// Scratch (allocation-free): fp16 copy of X with permuted channel pairs, fp16 W.
__device__ __align__(128) __half g_x16[(size_t)MAXN * CIN];           // 64 MiB
__device__ __align__(16) __half g_w16[KTAPS * COUT * CIN];            // [tap][n_mma][k'] 54 KiB

// Involution on input channel-pair index (s in 0..15): sigma(sigma(s)) == s
__device__ __forceinline__ int sigma(int s) { return ((s & 3) << 2) | (s >> 2); }

// Output-column permutation: MMA position p = t*8 + c (t=n-tile, c=2q+j) holds
// LOGICAL output column L(p) = (c>>1)*8 + 2t + (c&1). Bijection on 0..31.
// Effect: thread q's 8 outputs (t=0..3, j=0..1) = logical cols q*8..q*8+7 (contiguous).
__device__ __forceinline__ int out_perm(int p) {
    int t = p >> 3, c = p & 7;
    return ((c >> 1) << 3) + 2 * t + (c & 1);
}

// ---------------- Fused prep: X convert + W convert ----------------
// 8 threads per row; each thread: one float4 (16B) __ldcs load + two 8B stores.
__global__ void prep_kernel(const float4* __restrict__ x4,
                            const float* __restrict__ w, int n) {
    long long tid = (long long)blockIdx.x * blockDim.x + threadIdx.x;
    long long total = (long long)n * 8;
    if (tid < total) {
        int i = (int)(tid >> 3);
        int u = (int)(tid & 7);
        float4 v = __ldcs(x4 + (size_t)i * 8 + u);
        int s0 = sigma(2 * u);
        int s1 = sigma(2 * u + 1);
        __half2* dst = (__half2*)g_x16 + (size_t)i * 16;
        dst[s0] = __floats2half2_rn(v.x, v.y);
        dst[s1] = __floats2half2_rn(v.z, v.w);
    }
    // W conversion (first 54 blocks of 512 threads): k'-permuted (sigma) AND
    // n-permuted (out_perm) so epilogue stores are contiguous per thread.
    if (blockIdx.x < (KTAPS * COUT * CIN + 511) / 512) {
        int e = blockIdx.x * 512 + threadIdx.x;
        if (e < KTAPS * COUT * CIN) {
            int tap = e / (COUT * CIN);
            int rem = e % (COUT * CIN);
            int nn  = rem / CIN;               // MMA n position
            int kp  = rem % CIN;               // permuted k position
            int s   = kp >> 1, bit = kp & 1;
            int c   = 2 * sigma(s) + bit;      // original input channel
            int nl  = out_perm(nn);            // logical output channel
            g_w16[e] = __float2half_rn(w[(size_t)tap * CIN * COUT + (size_t)c * COUT + nl]);
        }
    }
}

// ---------------- fp16 MMA m16n8k16, fp32 accumulate ----------------
__device__ __forceinline__ void mma16816(float c[4],
                                         uint32_t a0, uint32_t a1, uint32_t a2, uint32_t a3,
                                         uint32_t b0, uint32_t b1) {
    asm("mma.sync.aligned.m16n8k16.row.col.f32.f16.f16.f32 "
        "{%0,%1,%2,%3}, {%4,%5,%6,%7}, {%8,%9}, {%0,%1,%2,%3};\n"
        : "+f"(c[0]), "+f"(c[1]), "+f"(c[2]), "+f"(c[3])
        : "r"(a0), "r"(a1), "r"(a2), "r"(a3), "r"(b0), "r"(b1));
}

// ---------------- Main: frozen R11 loop; PDL prologue; contiguous STG.128 epilogue ----
// smem: [0, 55296)          fp16 W (uint4 view, [tap][n-tile-row][16B])
//       [55296, 82944)      int32 neighbor BYTE OFFSETS (idx*64) [256 rows][27 taps]
#define W_SMEM     55296
#define SMEM_BYTES (W_SMEM + MBLOCK * KTAPS * 4)

__global__ __launch_bounds__(NTHREADS, 2)
void conv_main_kernel(const void* __restrict__ nbr_raw,
                      const float* __restrict__ bias,
                      float* __restrict__ out, int n, int ntiles) {
    extern __shared__ uint8_t smem[];
    uint4* w_s4  = (uint4*)smem;
    int*   nbr_s = (int*)(smem + W_SMEM);

    const int tid = threadIdx.x;

    // --- block-local nbr dtype detect (reads harness input only, pre-PDL-wait) ---
    int nz = 0;
    {
        const int* words = (const int*)nbr_raw;
        nz |= words[2 * (tid * 2 + 0) + 1];
        nz |= words[2 * (tid * 2 + 1) + 1];
    }
    const int is64 = __syncthreads_or(nz != 0) ? 0 : 1;

    // Staging: full tiles are layout-identical to source -> division-free.
    #define STAGE_NBR(i0_) do {                                                    \
        if ((i0_) + MBLOCK <= n) {                                                 \
            if (is64) {                                                            \
                const long long* g_ = (const long long*)nbr_raw + (size_t)(i0_) * KTAPS; \
                for (int t_ = tid; t_ < MBLOCK * KTAPS; t_ += NTHREADS)            \
                    nbr_s[t_] = ((int)__ldcs(g_ + t_)) << 6;                       \
            } else {                                                               \
                const int* g_ = (const int*)nbr_raw + (size_t)(i0_) * KTAPS;       \
                for (int t_ = tid; t_ < MBLOCK * KTAPS; t_ += NTHREADS)            \
                    nbr_s[t_] = __ldcs(g_ + t_) << 6;                              \
            }                                                                      \
        } else {                                                                   \
            if (is64) {                                                            \
                const long long* g_ = (const long long*)nbr_raw + (size_t)(i0_) * KTAPS; \
                for (int t_ = tid; t_ < MBLOCK * KTAPS; t_ += NTHREADS) {          \
                    int r_ = t_ / KTAPS;                                           \
                    long long v_ = ((i0_) + r_ < n) ? __ldcs(g_ + t_) : 0;         \
                    nbr_s[t_] = ((int)v_) << 6;                                    \
                }                                                                  \
            } else {                                                               \
                const int* g_ = (const int*)nbr_raw + (size_t)(i0_) * KTAPS;       \
                for (int t_ = tid; t_ < MBLOCK * KTAPS; t_ += NTHREADS) {          \
                    int r_ = t_ / KTAPS;                                           \
                    int v_ = ((i0_) + r_ < n) ? __ldcs(g_ + t_) : 0;               \
                    nbr_s[t_] = v_ << 6;                                           \
                }                                                                  \
            }                                                                      \
        }                                                                          \
    } while (0)

    // Pre-stage tile 0's neighbors (input-only) while prep may still be running.
    STAGE_NBR(blockIdx.x * MBLOCK);

    // Wait for prep grid (g_x16, g_w16) before touching its outputs.
    asm volatile("griddepcontrol.wait;" ::: "memory");

    // Stage W once per persistent block (3456 uint4, coalesced)
    const uint4* wg4 = (const uint4*)g_w16;
    #pragma unroll 4
    for (int t = tid; t < 3456; t += NTHREADS) w_s4[t] = wg4[t];

    const int lane = tid & 31;
    const int warp = tid >> 5;
    const int q    = lane & 3;     // quad column (16B chunk within row)
    const int nrow = lane >> 2;    // 0..7
    const int mb   = warp * 32;    // warp's 32 rows within tile

    // Bias fragment under the n-permutation: acc slot (t, j) holds logical
    // column q*8 + 2t + j -> bz[t] = bias[q*8 + 2t .. +1]
    float2 bz[4];
    #pragma unroll
    for (int t = 0; t < 4; t++)
        bz[t] = *(const float2*)(bias + q * 8 + 2 * t);

    const char* xb = (const char*)g_x16 + q * 16;   // this thread's chunk base

    #define LOAD_TAP(buf, k) do {                                           \
        _Pragma("unroll")                                                   \
        for (int mt = 0; mt < 2; mt++) {                                    \
            int rlo = mb + mt * 16 + nrow;                                  \
            int olo = nbr_s[rlo * KTAPS + (k)];                             \
            int ohi = nbr_s[(rlo + 8) * KTAPS + (k)];                       \
            (buf)[mt * 2 + 0] = *(const uint4*)(xb + olo);                  \
            (buf)[mt * 2 + 1] = *(const uint4*)(xb + ohi);                  \
        }                                                                   \
    } while (0)

    #define MMA_TAP(buf, k) do {                                            \
        _Pragma("unroll")                                                   \
        for (int t = 0; t < 4; t++) {                                       \
            uint4 bw = w_s4[(k) * 128 + (t * 8 + nrow) * 4 + q];            \
            _Pragma("unroll")                                               \
            for (int mt = 0; mt < 2; mt++) {                                \
                const uint4& lo = (buf)[mt * 2 + 0];                        \
                const uint4& hi = (buf)[mt * 2 + 1];                        \
                mma16816(acc[mt][t], lo.x, hi.x, lo.y, hi.y, bw.x, bw.y);   \
                mma16816(acc[mt][t], lo.z, hi.z, lo.w, hi.w, bw.z, bw.w);   \
            }                                                               \
        }                                                                   \
    } while (0)

    __syncthreads();   // W + tile-0 nbr visible to all warps

    for (int tile = blockIdx.x; tile < ntiles; tile += gridDim.x) {
        const int i0 = tile * MBLOCK;

        // Acc init = bias
        float acc[2][4][4];
        #pragma unroll
        for (int t = 0; t < 4; t++) {
            #pragma unroll
            for (int mt = 0; mt < 2; mt++) {
                acc[mt][t][0] = bz[t].x; acc[mt][t][1] = bz[t].y;
                acc[mt][t][2] = bz[t].x; acc[mt][t][3] = bz[t].y;
            }
        }

        // Depth-2 software pipeline, 3 rotating register buffers, KTAPS = 9*3.
        uint4 A0[4], A1[4], A2[4];
        LOAD_TAP(A0, 0);
        LOAD_TAP(A1, 1);

        #pragma unroll 1
        for (int kk = 0; kk < KTAPS / 3; kk++) {
            int k = kk * 3;
            if (k + 2 < KTAPS) LOAD_TAP(A2, k + 2);
            MMA_TAP(A0, k);
            if (k + 3 < KTAPS) LOAD_TAP(A0, k + 3);
            MMA_TAP(A1, k + 1);
            if (k + 4 < KTAPS) LOAD_TAP(A1, k + 4);
            MMA_TAP(A2, k + 2);
        }

        // Epilogue: thread's 8 outputs are logical cols q*8..q*8+7 -> 2x STG.128
        #pragma unroll
        for (int mt = 0; mt < 2; mt++) {
            #pragma unroll
            for (int half = 0; half < 2; half++) {
                int r = i0 + mb + mt * 16 + nrow + half * 8;
                if (r < n) {
                    float* po = out + (size_t)r * COUT + q * 8;
                    float4 v0, v1;
                    v0.x = acc[mt][0][half * 2 + 0]; v0.y = acc[mt][0][half * 2 + 1];
                    v0.z = acc[mt][1][half * 2 + 0]; v0.w = acc[mt][1][half * 2 + 1];
                    v1.x = acc[mt][2][half * 2 + 0]; v1.y = acc[mt][2][half * 2 + 1];
                    v1.z = acc[mt][3][half * 2 + 0]; v1.w = acc[mt][3][half * 2 + 1];
                    __stcs((float4*)po, v0);
                    __stcs((float4*)(po + 4), v1);
                }
            }
        }

        // Stage next tile's neighbors (loop-bottom, barrier-bracketed)
        const int nxt = tile + gridDim.x;
        if (nxt < ntiles) {
            __syncthreads();                 // all warps done reading nbr_s
            STAGE_NBR(nxt * MBLOCK);
            __syncthreads();                 // staged data visible
        }
    }
}

// ---------------- Launch ----------------
extern "C" void kernel_launch(void* const* d_in, const int* in_sizes, int n_in,
                              void* d_out, int out_size) {
    const float* x    = (const float*)d_in[0];       // [N, 32] f32
    const float* w    = (const float*)d_in[1];       // [27, 32, 32] f32
    const float* bias = (const float*)d_in[2];       // [32] f32
    const void*  nbr  = d_in[3];                     // [N, 27] int32 OR int64 (detected)
    float*       out  = (float*)d_out;               // [N, 32] f32

    const int n = in_sizes[0] / CIN;
    const int ntiles = (n + MBLOCK - 1) / MBLOCK;

    int nsm = 148;
    cudaDeviceGetAttribute(&nsm, cudaDevAttrMultiProcessorCount, 0);
    int grid = 2 * nsm;
    if (grid > ntiles) grid = ntiles;

    cudaFuncSetAttribute(conv_main_kernel,
                         cudaFuncAttributeMaxDynamicSharedMemorySize, SMEM_BYTES);

    {
        long long total = (long long)n * 8;          // 8 threads per row
        int blocks = (int)((total + 511) / 512);
        prep_kernel<<<blocks, 512>>>((const float4*)x, w, n);
    }

    // Main kernel with programmatic dependent launch: prologue (dtype detect +
    // tile-0 nbr staging) overlaps prep's tail; griddepcontrol.wait gates g_x16/g_w16.
    {
        cudaLaunchConfig_t cfg = {};
        cfg.gridDim  = dim3(grid, 1, 1);
        cfg.blockDim = dim3(NTHREADS, 1, 1);
        cfg.dynamicSmemBytes = SMEM_BYTES;
        cfg.stream = 0;
        cudaLaunchAttribute attr[1];
        attr[0].id = cudaLaunchAttributeProgrammaticStreamSerialization;
        attr[0].val.programmaticStreamSerializationAllowed = 1;
        cfg.attrs = attr;
        cfg.numAttrs = 1;
        cudaError_t err = cudaLaunchKernelEx(&cfg, conv_main_kernel,
                                             nbr, bias, out, n, ntiles);
        if (err != cudaSuccess) {
            conv_main_kernel<<<grid, NTHREADS, SMEM_BYTES>>>(nbr, bias, out, n, ntiles);
        }
    }
}